// round 2
// baseline (speedup 1.0000x reference)
#include <cuda_runtime.h>
#include <math.h>

// yolo_v3 head: out[b, cell, c] = f(x[b, c, cell])
//   B=32, cell in [0,4096), c = a*85 + d, a in [0,3), d in [0,85), stride=8
//
// Block = 32 cells x 255 channels.
//   Load phase : warp-uniform channel per iter -> divergence-free transform,
//                coalesced 128B row loads, conflict-free smem (stride 255).
//   Store phase: output span for 32 cells is 32640 B, contiguous AND
//                128B-aligned (32640 = 255*128) -> pure float4 linear copy.

#define WH      4096
#define NDIM    85
#define NCHAN   255
#define FSTRIDE 8.0f

__device__ __forceinline__ float fast_sigmoid(float v) {
    return __fdividef(1.0f, 1.0f + __expf(-v));
}

__global__ void __launch_bounds__(256) yolo_head_kernel(
    const float* __restrict__ x,        // [32, 255, 4096]
    const float* __restrict__ anchors,  // [3, 2]
    float* __restrict__ out)            // [32, 4096, 255]
{
    __shared__ float tile[32 * NCHAN];  // [cell_local][chan], 32640 B

    const int b     = blockIdx.y;
    const int cell0 = blockIdx.x * 32;

    const float* xb = x + ((size_t)b * NCHAN) * WH + cell0;

    const int warp = threadIdx.x >> 5;
    const int lane = threadIdx.x & 31;

    const int   cell = cell0 + lane;
    const float cx   = (float)(cell & 63);
    const float cy   = (float)(cell >> 6);

    // ---- Load + transform: 32 channels per warp, c warp-uniform per iter ----
    #pragma unroll 4
    for (int k = 0; k < 32; k++) {
        const int c = (k << 3) + warp;          // 0..255; c==255 skipped
        if (c < NCHAN) {
            const float v = __ldg(xb + (size_t)c * WH + lane);
            const int a = c / NDIM;             // warp-uniform
            const int d = c - a * NDIM;         // warp-uniform
            float r;
            if (d >= 4) {                       // uniform branch: 81/85 of iters
                r = fast_sigmoid(v);
            } else if (d == 0) {
                r = (fast_sigmoid(v) + cx) * FSTRIDE;
            } else if (d == 1) {
                r = (fast_sigmoid(v) + cy) * FSTRIDE;
            } else {                            // d == 2 or 3
                r = __expf(v) * __ldg(&anchors[a * 2 + (d - 2)]);
            }
            tile[lane * NCHAN + c] = r;         // stride 255: conflict-free
        }
    }
    __syncthreads();

    // ---- Store: linear float4 copy, coalesced + 16B-aligned ----
    const float4* ts = (const float4*)tile;
    float4* ob = (float4*)(out + ((size_t)b * WH + cell0) * NCHAN);
    #pragma unroll
    for (int i = threadIdx.x; i < (32 * NCHAN) / 4; i += 256)   // 2040 vec4
        ob[i] = ts[i];
}

extern "C" void kernel_launch(void* const* d_in, const int* in_sizes, int n_in,
                              void* d_out, int out_size) {
    const float* x       = (const float*)d_in[0];   // [32, 255, 64, 64] fp32
    const float* anchors = (const float*)d_in[1];   // [3, 2] fp32
    float* out           = (float*)d_out;           // [32, 12288, 85] fp32

    dim3 block(256, 1, 1);
    dim3 grid(WH / 32, 32, 1);                      // (128, 32) = 4096 blocks
    yolo_head_kernel<<<grid, block>>>(x, anchors, out);
}